// round 9
// baseline (speedup 1.0000x reference)
#include <cuda_runtime.h>
#include <cstdint>

// Q3 unpack -> float32 planes, warp-per-plane specialization.
//
// Block = 320 threads = 10 warps. Warp k extracts plane k (shift 27-3k).
// All 10 warps load the SAME 2KB input chunk (same SM -> L1 MSHR-merged,
// 1 DRAM fetch + 9 L1 hits), so DRAM reads stay 67MB. Each warp's stores
// form a single-plane contiguous 2KB stream (2 x st.global.cs.v8.b32 per
// lane-group) instead of the previous 10-way interleaved streams -> far
// better DRAM page locality on the 671MB write side.
//
// Chunk c covers input words [c*512, c*512+512). Lane l owns the 16
// consecutive words c*512 + l*16 .. +15 (4 x LDG.128 at 64B lane stride,
// L1-cached) and writes floats [c*512 + l*16, +16) of plane warp_id.

__device__ __forceinline__ void stg_cs_v8(float* p, const unsigned int* v)
{
    asm volatile(
        "st.global.cs.v8.b32 [%0], {%1, %2, %3, %4, %5, %6, %7, %8};"
        :: "l"(p),
           "r"(v[0]), "r"(v[1]), "r"(v[2]), "r"(v[3]),
           "r"(v[4]), "r"(v[5]), "r"(v[6]), "r"(v[7])
        : "memory");
}

__global__ void __launch_bounds__(320)
q3_unpack_warp_plane_kernel(const uint4* __restrict__ in,
                            float* __restrict__ out,
                            int n_words)  // total packed words (plane stride)
{
    const int c    = blockIdx.x;            // chunk index (512 words/chunk)
    const int warp = threadIdx.x >> 5;      // 0..9 -> plane
    const int lane = threadIdx.x & 31;

    // Load this lane's 16 consecutive words (4 x uint4). Default .ca load:
    // the same lines are read by all 10 warps of this block -> L1 reuse.
    const size_t vbase = (size_t)c * 128 + (size_t)lane * 4;  // uint4 index
    uint4 w[4];
#pragma unroll
    for (int j = 0; j < 4; ++j)
        w[j] = in[vbase + j];

    const unsigned int* ws = (const unsigned int*)w;  // 16 packed words

    const int s = 27 - 3 * warp;
    unsigned int v[16];
#pragma unroll
    for (int j = 0; j < 16; ++j)
        v[j] = __float_as_uint((float)((ws[j] >> s) & 7u));

    float* p = out + (size_t)warp * (size_t)n_words
                   + (size_t)c * 512 + (size_t)lane * 16;
    stg_cs_v8(p, v);
    stg_cs_v8(p + 8, v + 8);
}

extern "C" void kernel_launch(void* const* d_in, const int* in_sizes, int n_in,
                              void* d_out, int out_size)
{
    (void)n_in; (void)out_size;
    const int n_words = in_sizes[0];        // 4096*4096 = 16,777,216
    const int nchunk  = n_words / 512;      // 32,768 blocks

    const uint4* in = (const uint4*)d_in[0];
    float* out = (float*)d_out;

    q3_unpack_warp_plane_kernel<<<nchunk, 320>>>(in, out, n_words);
}

// round 11
// speedup vs baseline: 1.0505x; 1.0505x over previous
#include <cuda_runtime.h>
#include <cstdint>

// Q3 unpack -> float32 planes, smem-staged warp-per-plane.
// (Re-run: R9 submission hit a broker/container failure; kernel unchanged.)
//
// Block = 320 threads (10 warps) handles one 4096-word (16KB) input chunk:
//   1. All threads cooperatively stage the chunk into smem (coalesced
//      LDG.128 .cs -> DRAM reads stay 67MB total, no L1 amplification).
//   2. __syncthreads.
//   3. Warp k converts the whole chunk for plane k (shift 27-3k):
//      conflict-free LDS.128 (sbuf[j*32+lane]) -> 4x shift/and/I2F ->
//      STG.128 .cs. Each warp's stores form a single-plane CONTIGUOUS
//      16KB run, replacing the 10-way-interleaved write streams that
//      capped DRAM at ~73% -> better HBM page locality on the 671MB
//      write side.
//
// Occupancy: 6 blocks/SM x 320 thr = 94%, 96KB smem/SM.

static constexpr int CHUNK_WORDS = 4096;
static constexpr int CHUNK_VEC   = CHUNK_WORDS / 4;   // 1024 uint4 = 16KB
static constexpr int NTHREADS    = 320;

__global__ void __launch_bounds__(NTHREADS)
q3_unpack_smem_kernel(const uint4* __restrict__ in,
                      float* __restrict__ out,
                      int n_words)   // plane stride in elements
{
    __shared__ uint4 sbuf[CHUNK_VEC];

    const int warp = threadIdx.x >> 5;   // 0..9 -> plane
    const int lane = threadIdx.x & 31;
    const size_t chunk_base = (size_t)blockIdx.x * CHUNK_VEC;

    // Stage chunk into smem, coalesced, streaming.
    for (int idx = threadIdx.x; idx < CHUNK_VEC; idx += NTHREADS)
        sbuf[idx] = __ldcs(in + chunk_base + idx);
    __syncthreads();

    const int s = 27 - 3 * warp;
    float4* p = (float4*)(out + (size_t)warp * (size_t)n_words
                              + (size_t)blockIdx.x * CHUNK_WORDS);

#pragma unroll 4
    for (int j = 0; j < 32; ++j) {
        const uint4 w = sbuf[j * 32 + lane];   // conflict-free LDS.128
        float4 v;
        v.x = (float)((w.x >> s) & 7u);
        v.y = (float)((w.y >> s) & 7u);
        v.z = (float)((w.z >> s) & 7u);
        v.w = (float)((w.w >> s) & 7u);
        __stcs(p + j * 32 + lane, v);          // contiguous 512B/warp/store
    }
}

extern "C" void kernel_launch(void* const* d_in, const int* in_sizes, int n_in,
                              void* d_out, int out_size)
{
    (void)n_in; (void)out_size;
    const int n_words = in_sizes[0];               // 4096*4096 = 16,777,216
    const int blocks  = n_words / CHUNK_WORDS;     // 4096

    const uint4* in = (const uint4*)d_in[0];
    float* out = (float*)d_out;

    q3_unpack_smem_kernel<<<blocks, NTHREADS>>>(in, out, n_words);
}

// round 12
// speedup vs baseline: 1.0917x; 1.0392x over previous
#include <cuda_runtime.h>
#include <cstdint>

// Q3 unpack -> float32 planes. FINAL (revert to R5, measured best).
//
// Input:  4096x4096 int32; each word holds 10 x 3-bit fields at shifts
//         27,24,...,0.  Output: [10*4096, 4096] float32; plane k =
//         (float)((w >> (27-3k)) & 7), same linear layout as the input at
//         element offset k * n_words.
//
// Thread i handles 8 consecutive words (2 x LDG.128 .cs) and emits one
// 32-byte st.global.cs.v8.b32 per plane (1KB contiguous per warp per plane).
// Traffic: 67MB in + 671MB out, zero reuse.
//
// Measured across 4 structural variants (store width 16B/32B, default vs .cs
// policy, interleaved vs per-warp-contiguous streams via smem staging): all
// land at 70-74% DRAM / ~5.9-6.0 TB/s. That is the memory-system ceiling for
// this 10.5:1 write:read mix; this variant is the fastest (115.0us ncu) and
// the simplest (32 regs, no smem, no syncs).

__device__ __forceinline__ void stg_cs_v8(float* p,
                                          float v0, float v1, float v2, float v3,
                                          float v4, float v5, float v6, float v7)
{
    asm volatile(
        "st.global.cs.v8.b32 [%0], {%1, %2, %3, %4, %5, %6, %7, %8};"
        :: "l"(p),
           "r"(__float_as_uint(v0)), "r"(__float_as_uint(v1)),
           "r"(__float_as_uint(v2)), "r"(__float_as_uint(v3)),
           "r"(__float_as_uint(v4)), "r"(__float_as_uint(v5)),
           "r"(__float_as_uint(v6)), "r"(__float_as_uint(v7))
        : "memory");
}

__global__ void __launch_bounds__(256)
q3_unpack_f32_v8_kernel(const uint4* __restrict__ in,
                        float* __restrict__ out,
                        int nvec8)  // number of 8-word groups (= words/8)
{
    int i = blockIdx.x * blockDim.x + threadIdx.x;
    if (i >= nvec8) return;

    const uint4 a = __ldcs(in + 2 * (size_t)i);
    const uint4 b = __ldcs(in + 2 * (size_t)i + 1);

    const size_t plane = (size_t)nvec8 * 8;   // plane stride in floats
    float* o = out + (size_t)i * 8;

#pragma unroll
    for (int k = 0; k < 10; ++k) {
        const int s = 27 - 3 * k;
        stg_cs_v8(o + (size_t)k * plane,
                  (float)((a.x >> s) & 7u), (float)((a.y >> s) & 7u),
                  (float)((a.z >> s) & 7u), (float)((a.w >> s) & 7u),
                  (float)((b.x >> s) & 7u), (float)((b.y >> s) & 7u),
                  (float)((b.z >> s) & 7u), (float)((b.w >> s) & 7u));
    }
}

extern "C" void kernel_launch(void* const* d_in, const int* in_sizes, int n_in,
                              void* d_out, int out_size)
{
    (void)n_in; (void)out_size;
    const int n_words = in_sizes[0];      // 4096*4096 = 16,777,216
    const int nvec8   = n_words >> 3;     // 2,097,152

    const uint4* in = (const uint4*)d_in[0];
    float* out = (float*)d_out;

    const int threads = 256;
    const int blocks  = (nvec8 + threads - 1) / threads;  // 8192
    q3_unpack_f32_v8_kernel<<<blocks, threads>>>(in, out, nvec8);
}